// round 12
// baseline (speedup 1.0000x reference)
#include <cuda_runtime.h>
#include <cuda_fp16.h>

// Problem constants (fixed shapes for this problem instance)
#define NN 100000   // nodes
#define NE 800000   // edges
#define VC 256      // vocab
#define DM 256      // node dim == hidden == vocab
#define NM 10000    // masked outputs

#define SB 512
#define NSB ((NN + SB - 1) / SB)   // 196 scan blocks
#define NW2B 128                   // W2 cvt blocks (65536 elems / 512)

// ---------------- scratch (device globals; no allocation allowed) ----------
// g_dmn = [deg | masked | needed], zeroed by ONE cudaMemsetAsync (replaces k_init).
// deg counts EDGES into node (self-loop handled as +1 at use sites).
__device__ int   g_dmn[3 * NN];
#define DEG(i)    g_dmn[(i)]
#define MASKED(i) g_dmn[NN + (i)]
#define NEEDED(i) g_dmn[2 * NN + (i)]
__device__ int   g_cur[NN];     // seeded to CSR offset in scanBC
__device__ int   g_off[NN];
__device__ int   g_bsum[NSB];
__device__ float g_dinv[NN];
__device__ __align__(8)  int2   g_nv[NN];          // {x | masked<<31, dinv_bits}
__device__ __align__(16) __half g_EWh[VC * DM];    // emb @ W1, fp16 (128 KB)
__device__ __align__(16) __half g_W2p[DM * VC];    // W2 fp16, k-quad packed (128 KB)
__device__ __align__(16) __half g_out1h[NN * DM];  // relu(layer-1), fp16 (51 MB)
__device__ __align__(16) float  g_aggc[NM * DM];   // layer-2 aggregate (10 MB)
__device__ __align__(16) int4   g_edge[NE];        // {x[src], src, coef_bits, 0}

// ---------------- kernels ---------------------------------------------------

// degree count (first NE threads) + mask marking (next NM)
__global__ void k_degmark(const int* __restrict__ ei, const int* __restrict__ mask) {
    int t = blockIdx.x * blockDim.x + threadIdx.x;
    if (t < NE) {
        atomicAdd(&DEG(ei[NE + t]), 1);
    } else if (t < NE + NM) {
        int n = mask[t - NE];
        MASKED(n) = 1;
        NEEDED(n) = 1;            // self term of layer-2 reads out1[node]
    }
}

// blocks [0,NSB): scanA | [NSB,NSB+VC): EW row | [NSB+VC,NSB+VC+NW2B): W2 cvt
__global__ void k_scanAew(const float* __restrict__ emb, const float* __restrict__ W1,
                          const float* __restrict__ W2) {
    __shared__ float sf[SB];
    if (blockIdx.x < NSB) {
        // ---- scanA: per-block exclusive scan of deg (edge counts) ----
        int* s = reinterpret_cast<int*>(sf);
        int i = blockIdx.x * SB + threadIdx.x;
        int v = (i < NN) ? DEG(i) : 0;
        s[threadIdx.x] = v;
        __syncthreads();
        for (int o = 1; o < SB; o <<= 1) {
            int t = (threadIdx.x >= o) ? s[threadIdx.x - o] : 0;
            __syncthreads();
            s[threadIdx.x] += t;
            __syncthreads();
        }
        int inc = s[threadIdx.x];
        if (i < NN) g_off[i] = inc - v;             // exclusive (pre-bsum)
        if (threadIdx.x == SB - 1) g_bsum[blockIdx.x] = inc;
    } else if (blockIdx.x < NSB + VC) {
        // ---- EW row: g_EWh[r] = fp16(emb[r] @ W1) ----
        int r = blockIdx.x - NSB;
        int c = threadIdx.x;
        if (c < DM) sf[c] = emb[r * DM + c];
        __syncthreads();
        if (c >= DM) return;
        float acc = 0.f;
#pragma unroll 8
        for (int k = 0; k < DM; k++) acc += sf[k] * W1[k * DM + c];
        g_EWh[r * DM + c] = __float2half(acc);
    } else {
        // ---- W2 cvt + k-quad pack: W2p[(kk*256+c)*4+i] = fp16(W2[(4kk+i)*256+c])
        int o = (blockIdx.x - NSB - VC) * SB + threadIdx.x;   // 0..65535
        int i = o & 3;
        int c = (o >> 2) & (DM - 1);
        int kk = o >> 10;
        g_W2p[o] = __float2half(W2[(4 * kk + i) * DM + c]);
    }
}

// fused scanB+scanC+dinv; seeds g_cur = final offset; builds node record g_nv
__global__ void k_scanBC(const int* __restrict__ x) {
    __shared__ int s[256];
    int t = threadIdx.x;
    if (t < 256) {
        int v = (t < NSB) ? g_bsum[t] : 0;
        s[t] = v;
    }
    __syncthreads();
    for (int o = 1; o < 256; o <<= 1) {
        int u = 0;
        if (t < 256 && t >= o) u = s[t - o];
        __syncthreads();
        if (t < 256) s[t] += u;
        __syncthreads();
    }
    int pre = (blockIdx.x == 0) ? 0 : s[blockIdx.x - 1];
    int i = blockIdx.x * SB + t;
    if (i < NN) {
        int off = g_off[i] + pre;
        g_off[i] = off;
        g_cur[i] = off;                             // place bumps this directly
        float di = rsqrtf((float)(DEG(i) + 1));     // +1 = self loop
        g_dinv[i] = di;
        int xm = x[i] | (MASKED(i) << 31);          // x in [0,256): bit31 free
        g_nv[i] = make_int2(xm, __float_as_int(di));
    }
}

// place edges into CSR slots (single 16B scattered store); flag needed srcs
__global__ void k_place(const int* __restrict__ ei) {
    int e = blockIdx.x * blockDim.x + threadIdx.x;
    if (e >= NE) return;
    int s = ei[e];
    int d = ei[NE + e];
    int2 nvs = g_nv[s];
    int2 nvd = g_nv[d];
    float coef = __int_as_float(nvs.y) * __int_as_float(nvd.y);
    int slot = atomicAdd(&g_cur[d], 1);
    g_edge[slot] = make_int4(nvs.x & 0x7fffffff, s, __float_as_int(coef), 0);
    if (nvd.x < 0) NEEDED(s) = 1;                   // dst is masked
}

// layer-1 gather: out1h[i] = fp16(relu(b1 + dinv^2*EW[x[i]] + sum coef*EW[x[src]]))
// 64 threads/node; EW fp16 (L1-resident), fp32 accumulate.
// Edge loop unrolled 2x with INDEPENDENT accumulator chains (MLP=2).
__global__ void k_gather1(const int* __restrict__ x, const float* __restrict__ b1) {
    int node = blockIdx.x * 4 + (threadIdx.x >> 6);
    if (node >= NN) return;
    if (!NEEDED(node)) return;                      // uniform per 64-thread group
    int q = threadIdx.x & 63;

    const uint2* EW2 = reinterpret_cast<const uint2*>(g_EWh);  // 4 halves/thread
    float di = g_dinv[node];
    float dd = di * di;

    uint2 w0u = EW2[x[node] * 64 + q];
    float2 f0a = __half22float2(*reinterpret_cast<__half2*>(&w0u.x));
    float2 f0b = __half22float2(*reinterpret_cast<__half2*>(&w0u.y));
    float4 bb = reinterpret_cast<const float4*>(b1)[q];
    float4 accA = make_float4(bb.x + dd * f0a.x, bb.y + dd * f0a.y,
                              bb.z + dd * f0b.x, bb.w + dd * f0b.y);
    float4 accB = make_float4(0.f, 0.f, 0.f, 0.f);

    int k   = g_off[node];
    int end = k + DEG(node);
    for (; k + 1 < end; k += 2) {
        int4 r0 = g_edge[k];                        // independent broadcast loads
        int4 r1 = g_edge[k + 1];
        float c0 = __int_as_float(r0.z);
        float c1 = __int_as_float(r1.z);
        uint2 wu0 = EW2[r0.x * 64 + q];             // both rows in flight
        uint2 wu1 = EW2[r1.x * 64 + q];
        float2 a0 = __half22float2(*reinterpret_cast<__half2*>(&wu0.x));
        float2 b0 = __half22float2(*reinterpret_cast<__half2*>(&wu0.y));
        float2 a1 = __half22float2(*reinterpret_cast<__half2*>(&wu1.x));
        float2 b1v = __half22float2(*reinterpret_cast<__half2*>(&wu1.y));
        accA.x += c0 * a0.x; accA.y += c0 * a0.y;
        accA.z += c0 * b0.x; accA.w += c0 * b0.y;
        accB.x += c1 * a1.x; accB.y += c1 * a1.y;
        accB.z += c1 * b1v.x; accB.w += c1 * b1v.y;
    }
    if (k < end) {
        int4 r0 = g_edge[k];
        float c0 = __int_as_float(r0.z);
        uint2 wu0 = EW2[r0.x * 64 + q];
        float2 a0 = __half22float2(*reinterpret_cast<__half2*>(&wu0.x));
        float2 b0 = __half22float2(*reinterpret_cast<__half2*>(&wu0.y));
        accA.x += c0 * a0.x; accA.y += c0 * a0.y;
        accA.z += c0 * b0.x; accA.w += c0 * b0.y;
    }
    accA.x += accB.x; accA.y += accB.y; accA.z += accB.z; accA.w += accB.w;

    // store relu(acc) fp16 — gather2 only ever consumes relu(out1)
    __half2 oa = __floats2half2_rn(fmaxf(accA.x, 0.f), fmaxf(accA.y, 0.f));
    __half2 ob = __floats2half2_rn(fmaxf(accA.z, 0.f), fmaxf(accA.w, 0.f));
    uint2 ou;
    ou.x = *reinterpret_cast<unsigned*>(&oa);
    ou.y = *reinterpret_cast<unsigned*>(&ob);
    reinterpret_cast<uint2*>(g_out1h)[node * 64 + q] = ou;
}

// layer-2 gather, masked entries only (compact j-indexed output), MLP=2:
//   aggc[j] = dinv^2*h1[node] + sum coef*h1[src]   (h1 already relu'd)
__global__ void k_gather2(const int* __restrict__ mask) {
    int gid = blockIdx.x * blockDim.x + threadIdx.x;
    int j = gid >> 6;
    if (j >= NM) return;
    int q = gid & 63;
    int node = mask[j];

    const uint2* O2 = reinterpret_cast<const uint2*>(g_out1h);
    float di = g_dinv[node];
    float dd = di * di;

    uint2 hu = O2[node * 64 + q];
    float2 ha = __half22float2(*reinterpret_cast<__half2*>(&hu.x));
    float2 hb = __half22float2(*reinterpret_cast<__half2*>(&hu.y));
    float4 accA = make_float4(dd * ha.x, dd * ha.y, dd * hb.x, dd * hb.y);
    float4 accB = make_float4(0.f, 0.f, 0.f, 0.f);

    int k   = g_off[node];
    int end = k + DEG(node);
    for (; k + 1 < end; k += 2) {
        int4 r0 = g_edge[k];
        int4 r1 = g_edge[k + 1];
        float c0 = __int_as_float(r0.z);
        float c1 = __int_as_float(r1.z);
        uint2 su0 = O2[r0.y * 64 + q];              // independent scattered rows
        uint2 su1 = O2[r1.y * 64 + q];
        float2 s0a = __half22float2(*reinterpret_cast<__half2*>(&su0.x));
        float2 s0b = __half22float2(*reinterpret_cast<__half2*>(&su0.y));
        float2 s1a = __half22float2(*reinterpret_cast<__half2*>(&su1.x));
        float2 s1b = __half22float2(*reinterpret_cast<__half2*>(&su1.y));
        accA.x += c0 * s0a.x; accA.y += c0 * s0a.y;
        accA.z += c0 * s0b.x; accA.w += c0 * s0b.y;
        accB.x += c1 * s1a.x; accB.y += c1 * s1a.y;
        accB.z += c1 * s1b.x; accB.w += c1 * s1b.y;
    }
    if (k < end) {
        int4 r0 = g_edge[k];
        float c0 = __int_as_float(r0.z);
        uint2 su0 = O2[r0.y * 64 + q];
        float2 s0a = __half22float2(*reinterpret_cast<__half2*>(&su0.x));
        float2 s0b = __half22float2(*reinterpret_cast<__half2*>(&su0.y));
        accA.x += c0 * s0a.x; accA.y += c0 * s0a.y;
        accA.z += c0 * s0b.x; accA.w += c0 * s0b.y;
    }
    accA.x += accB.x; accA.y += accB.y; accA.z += accB.z; accA.w += accB.w;
    reinterpret_cast<float4*>(g_aggc)[j * 64 + q] = accA;
}

// out[j] = log_softmax(aggc[j] @ W2 + b2); W2 fp16 k-quad packed, FFMA2 inner loop.
// FROWS=16 (FROWS=32 spills acc[] -> +40us, established R5-R8)
#define FROWS 16
__global__ void k_final(const float* __restrict__ b2, float* __restrict__ out) {
    __shared__ float A[FROWS * DM];
    __shared__ float red[8];
    int c  = threadIdx.x;
    int j0 = blockIdx.x * FROWS;

#pragma unroll
    for (int r = 0; r < FROWS; r++)
        A[r * DM + c] = g_aggc[(j0 + r) * DM + c];
    __syncthreads();

    float bc = b2[c];
    unsigned long long acc2[FROWS];
    unsigned long long bcpk;
    asm("mov.b64 %0, {%1, %2};" : "=l"(bcpk) : "f"(bc), "f"(0.f));
#pragma unroll
    for (int r = 0; r < FROWS; r++) acc2[r] = bcpk;

    const ulonglong2* A8 = reinterpret_cast<const ulonglong2*>(A);  // {f0,f1},{f2,f3}
    const uint2* W2p2 = reinterpret_cast<const uint2*>(g_W2p);
#pragma unroll 4
    for (int kk = 0; kk < DM / 4; kk++) {
        uint2 wu = W2p2[kk * DM + c];               // 4 halves: k=4kk..4kk+3, col c
        float2 w01 = __half22float2(*reinterpret_cast<__half2*>(&wu.x));
        float2 w23 = __half22float2(*reinterpret_cast<__half2*>(&wu.y));
        unsigned long long wp01, wp23;
        asm("mov.b64 %0, {%1, %2};" : "=l"(wp01) : "f"(w01.x), "f"(w01.y));
        asm("mov.b64 %0, {%1, %2};" : "=l"(wp23) : "f"(w23.x), "f"(w23.y));
#pragma unroll
        for (int r = 0; r < FROWS; r++) {
            ulonglong2 av = A8[r * (DM / 4) + kk];  // LDS.128 broadcast
            asm("fma.rn.f32x2 %0, %1, %2, %0;" : "+l"(acc2[r]) : "l"(av.x), "l"(wp01));
            asm("fma.rn.f32x2 %0, %1, %2, %0;" : "+l"(acc2[r]) : "l"(av.y), "l"(wp23));
        }
    }

    float acc[FROWS];
#pragma unroll
    for (int r = 0; r < FROWS; r++) {
        float lo, hi;
        asm("mov.b64 {%0, %1}, %2;" : "=f"(lo), "=f"(hi) : "l"(acc2[r]));
        acc[r] = lo + hi;
    }

    int lane = c & 31, wid = c >> 5;
#pragma unroll 1
    for (int r = 0; r < FROWS; r++) {
        float v = acc[r];
#pragma unroll
        for (int o = 16; o; o >>= 1) v = fmaxf(v, __shfl_xor_sync(0xffffffffu, v, o));
        if (lane == 0) red[wid] = v;
        __syncthreads();
        float m = red[0];
#pragma unroll
        for (int w = 1; w < 8; w++) m = fmaxf(m, red[w]);
        __syncthreads();
        float s = __expf(acc[r] - m);
#pragma unroll
        for (int o = 16; o; o >>= 1) s += __shfl_xor_sync(0xffffffffu, s, o);
        if (lane == 0) red[wid] = s;
        __syncthreads();
        float tot = red[0];
#pragma unroll
        for (int w = 1; w < 8; w++) tot += red[w];
        __syncthreads();
        out[(j0 + r) * DM + c] = acc[r] - m - logf(tot);
    }
}

// ---------------- launch -----------------------------------------------------
extern "C" void kernel_launch(void* const* d_in, const int* in_sizes, int n_in,
                              void* d_out, int out_size) {
    const int*   x    = (const int*)d_in[0];   // (100000,1) int32
    const int*   ei   = (const int*)d_in[1];   // (2,800000) int32: [src | dst]
    const int*   mask = (const int*)d_in[2];   // (10000,)   int32
    const float* emb  = (const float*)d_in[3]; // (256,256)
    const float* W1   = (const float*)d_in[4]; // (256,256)
    const float* b1   = (const float*)d_in[5]; // (256,)
    const float* W2   = (const float*)d_in[6]; // (256,256)
    const float* b2   = (const float*)d_in[7]; // (256,)
    float* out = (float*)d_out;                // (10000,256)

    (void)in_sizes; (void)n_in; (void)out_size;

    // zero deg|masked|needed in one memset node (replaces k_init kernel)
    void* dmn_ptr = nullptr;
    cudaGetSymbolAddress(&dmn_ptr, g_dmn);
    cudaMemsetAsync(dmn_ptr, 0, sizeof(int) * 3 * NN);

    k_degmark<<<(NE + NM + 255) / 256, 256>>>(ei, mask);
    k_scanAew<<<NSB + VC + NW2B, SB>>>(emb, W1, W2);
    k_scanBC <<<NSB, SB>>>(x);
    k_place  <<<(NE + 255) / 256, 256>>>(ei);
    k_gather1<<<(NN + 3) / 4, 256>>>(x, b1);
    k_gather2<<<(NM * 64 + 255) / 256, 256>>>(mask);
    k_final  <<<NM / FROWS, DM>>>(b2, out);
}